// round 12
// baseline (speedup 1.0000x reference)
#include <cuda_runtime.h>
#include <cuda_bf16.h>
#include <cuda_fp16.h>
#include <cstdint>
#include <cstring>

// GCNConv: out = D_in^{-1/2} * A * (D_out^{-1/2} * (X @ W)) + bias
// Stage 0: bake W -> fp16 frag layout, kstep-paired uint4 (32KB, L1-resident)
// Stage 1: zero-smem fp16 mma.sync GEMM; ALL A loaded+converted up front,
//          nt-outer/sp-inner loop (acc live range = 4 regs, store per nt)
// Stage 2: gather-aggregate, deg==16 fast path with 16-wide MLP (R11)

#define MAX_N 100000

__device__ __half g_h[(size_t)MAX_N * 128];
// frag layout: [ntile 0..15][spair 0..3][lane 0..31] =
//   {even-kstep fh0, even fh1, odd fh0, odd fh1}
__device__ uint4  g_wfrag[16 * 4 * 32];

// ---------------------------------------------------------------------------
// helpers
// ---------------------------------------------------------------------------
__device__ __forceinline__ unsigned h2u(__half2 v) {
    unsigned r;
    memcpy(&r, &v, 4);
    return r;
}

__device__ __forceinline__ unsigned cvt_f16x2(float2 v) {
    unsigned r;
    asm("cvt.rn.f16x2.f32 %0, %1, %2;" : "=r"(r) : "f"(v.y), "f"(v.x));
    return r;
}

__device__ __forceinline__ void mma_f16(float* c, const unsigned* a,
                                        unsigned b0, unsigned b1) {
    asm volatile(
        "mma.sync.aligned.m16n8k16.row.col.f32.f16.f16.f32 "
        "{%0,%1,%2,%3}, {%4,%5,%6,%7}, {%8,%9}, {%0,%1,%2,%3};"
        : "+f"(c[0]), "+f"(c[1]), "+f"(c[2]), "+f"(c[3])
        : "r"(a[0]), "r"(a[1]), "r"(a[2]), "r"(a[3]), "r"(b0), "r"(b1));
}

// ---------------------------------------------------------------------------
// Stage 0: bake W [k][n] fp32 into kstep-paired fp16 frag layout.
// ---------------------------------------------------------------------------
__global__ __launch_bounds__(256) void wfrag_kernel(const float* __restrict__ w) {
    int idx = blockIdx.x * 256 + threadIdx.x;   // 0..2047
    int lane = idx & 31;
    int sp   = (idx >> 5) & 3;
    int ntile = idx >> 7;
    int lg = lane >> 2;
    int lt = lane & 3;
    int nn = ntile * 8 + lg;
    int k0 = (2 * sp) * 16 + 2 * lt;

    float e00 = w[(k0    ) * 128 + nn];
    float e01 = w[(k0 + 1) * 128 + nn];
    float e10 = w[(k0 + 8) * 128 + nn];
    float e11 = w[(k0 + 9) * 128 + nn];
    float o00 = w[(k0 + 16) * 128 + nn];
    float o01 = w[(k0 + 17) * 128 + nn];
    float o10 = w[(k0 + 24) * 128 + nn];
    float o11 = w[(k0 + 25) * 128 + nn];

    g_wfrag[idx] = make_uint4(h2u(__floats2half2_rn(e00, e01)),
                              h2u(__floats2half2_rn(e10, e11)),
                              h2u(__floats2half2_rn(o00, o01)),
                              h2u(__floats2half2_rn(o10, o11)));
}

// ---------------------------------------------------------------------------
// Stage 1 GEMM body. Warp owns rows [base, base+16) x cols [0,128).
// A: 32 LDG.64 up front -> 32 fp16x2 regs (a[sp][even/odd][4]).
// Loop: nt outer (16), sp inner (4), 2 MMAs per sp; store per nt.
// ---------------------------------------------------------------------------
template <bool FULL>
__device__ __forceinline__ void gemm_body(
    const float* __restrict__ x,
    const uint4* __restrict__ wfrag,
    const int*   __restrict__ colptr,
    __half*      __restrict__ h,
    int n, int rowbase, int lane)
{
    const int lg = lane >> 2;
    const int lt = lane & 3;
    const int r0 = rowbase + lg;
    const int r1 = r0 + 8;
    const bool v0 = FULL || (r0 < n);
    const bool v1 = FULL || (r1 < n);

    const float2* xr0 = reinterpret_cast<const float2*>(x + (size_t)r0 * 128);
    const float2* xr1 = reinterpret_cast<const float2*>(x + (size_t)r1 * 128);
    const float2 z2 = make_float2(0.f, 0.f);

    // ---- load ALL A: 8 ksteps x {r0_klo, r1_klo, r0_khi, r1_khi} ----
    float2 raw[8][4];
    #pragma unroll
    for (int s = 0; s < 8; s++) {
        const int kq = s * 8 + lt;
        raw[s][0] = v0 ? __ldg(&xr0[kq])     : z2;
        raw[s][1] = v1 ? __ldg(&xr1[kq])     : z2;
        raw[s][2] = v0 ? __ldg(&xr0[kq + 4]) : z2;
        raw[s][3] = v1 ? __ldg(&xr1[kq + 4]) : z2;
    }

    // degree scales (overlap with loads)
    float s0 = 0.f, s1 = 0.f;
    if (v0) {
        float d = (float)(colptr[r0 + 1] - colptr[r0]);
        s0 = (d > 0.f) ? rsqrtf(d) : 0.f;
    }
    if (v1) {
        float d = (float)(colptr[r1 + 1] - colptr[r1]);
        s1 = (d > 0.f) ? rsqrtf(d) : 0.f;
    }

    // ---- convert all A to fp16x2: a[sp][0..3]=even kstep, a[sp][4..7]=odd ----
    unsigned a[4][8];
    #pragma unroll
    for (int sp = 0; sp < 4; sp++) {
        #pragma unroll
        for (int j = 0; j < 4; j++) {
            a[sp][j]     = cvt_f16x2(raw[2 * sp][j]);
            a[sp][4 + j] = cvt_f16x2(raw[2 * sp + 1][j]);
        }
    }

    // ---- main loop: nt outer, sp inner; immediate scaled store ----
    const uint4* wf = wfrag + lane;
    #pragma unroll
    for (int nt = 0; nt < 16; nt++) {
        float acc[4] = {0.f, 0.f, 0.f, 0.f};
        #pragma unroll
        for (int sp = 0; sp < 4; sp++) {
            uint4 b = wf[(nt * 4 + sp) * 32];
            mma_f16(acc, &a[sp][0], b.x, b.y);
            mma_f16(acc, &a[sp][4], b.z, b.w);
        }
        const int col = nt * 8 + 2 * lt;
        if (v0) {
            __half2 p = __floats2half2_rn(acc[0] * s0, acc[1] * s0);
            *reinterpret_cast<unsigned*>(&h[(size_t)r0 * 128 + col]) = h2u(p);
        }
        if (v1) {
            __half2 p = __floats2half2_rn(acc[2] * s1, acc[3] * s1);
            *reinterpret_cast<unsigned*>(&h[(size_t)r1 * 128 + col]) = h2u(p);
        }
    }
}

__global__ __launch_bounds__(256, 2) void gemm_mma_kernel(
    const float* __restrict__ x,
    const uint4* __restrict__ wfrag,
    const int*   __restrict__ colptr,
    __half*      __restrict__ h,
    int n)
{
    const int tid  = threadIdx.x;
    const int wid  = tid >> 5;
    const int lane = tid & 31;
    const int rowbase = blockIdx.x * 128 + wid * 16;

    if ((blockIdx.x + 1) * 128 <= n)
        gemm_body<true>(x, wfrag, colptr, h, n, rowbase, lane);
    else
        gemm_body<false>(x, wfrag, colptr, h, n, rowbase, lane);
}

// ---------------------------------------------------------------------------
// Stage 2: aggregation (identical to R11). 8 nodes/block, 32 lanes/node,
// deg==16 fast path with 16 gathers in flight.
// ---------------------------------------------------------------------------
__global__ __launch_bounds__(256) void aggregate_kernel(
    const __half* __restrict__ h,
    const int*    __restrict__ rowptr,
    const int*    __restrict__ colind,
    const float*  __restrict__ bias,
    float*        __restrict__ out,
    int n)
{
    const int node = blockIdx.x * 8 + (threadIdx.x >> 5);
    const int lane = threadIdx.x & 31;
    if (node >= n) return;

    const int beg = rowptr[node];
    const int end = rowptr[node + 1];
    const uint2* h2 = reinterpret_cast<const uint2*>(h);

    float4 a0 = make_float4(0.f, 0.f, 0.f, 0.f);
    float4 a1 = make_float4(0.f, 0.f, 0.f, 0.f);

    if (end - beg == 16 && (beg & 3) == 0) {
        const int4* cp = reinterpret_cast<const int4*>(colind + beg);
        int4 c0 = __ldg(cp + 0);
        int4 c1 = __ldg(cp + 1);
        int4 c2 = __ldg(cp + 2);
        int4 c3 = __ldg(cp + 3);
        int idx[16] = {c0.x, c0.y, c0.z, c0.w, c1.x, c1.y, c1.z, c1.w,
                       c2.x, c2.y, c2.z, c2.w, c3.x, c3.y, c3.z, c3.w};
        uint2 v[16];
        #pragma unroll
        for (int i = 0; i < 16; i++)
            v[i] = h2[(size_t)idx[i] * 32 + lane];
        #pragma unroll
        for (int i = 0; i < 16; i += 2) {
            float2 f;
            f = __half22float2(*reinterpret_cast<__half2*>(&v[i].x));
            a0.x += f.x; a0.y += f.y;
            f = __half22float2(*reinterpret_cast<__half2*>(&v[i].y));
            a0.z += f.x; a0.w += f.y;
            f = __half22float2(*reinterpret_cast<__half2*>(&v[i+1].x));
            a1.x += f.x; a1.y += f.y;
            f = __half22float2(*reinterpret_cast<__half2*>(&v[i+1].y));
            a1.z += f.x; a1.w += f.y;
        }
    } else {
        for (int e = beg; e < end; e++) {
            int i0 = __ldg(&colind[e]);
            uint2 u0 = h2[(size_t)i0 * 32 + lane];
            float2 f;
            f = __half22float2(*reinterpret_cast<__half2*>(&u0.x));
            a0.x += f.x; a0.y += f.y;
            f = __half22float2(*reinterpret_cast<__half2*>(&u0.y));
            a0.z += f.x; a0.w += f.y;
        }
    }

    float4 acc;
    acc.x = a0.x + a1.x;
    acc.y = a0.y + a1.y;
    acc.z = a0.z + a1.z;
    acc.w = a0.w + a1.w;

    float deg = (float)(end - beg);
    float s = (deg > 0.f) ? rsqrtf(deg) : 0.f;

    float4 b = reinterpret_cast<const float4*>(bias)[lane];
    float4 o;
    o.x = acc.x * s + b.x;
    o.y = acc.y * s + b.y;
    o.z = acc.z * s + b.z;
    o.w = acc.w * s + b.w;

    reinterpret_cast<float4*>(out)[(size_t)node * 32 + lane] = o;
}

// ---------------------------------------------------------------------------
// launch
// ---------------------------------------------------------------------------
extern "C" void kernel_launch(void* const* d_in, const int* in_sizes, int n_in,
                              void* d_out, int out_size)
{
    const float* x      = (const float*)d_in[0];
    const float* weight = (const float*)d_in[1];
    const float* bias   = (const float*)d_in[2];
    const int*   rowptr = (const int*)  d_in[3];
    const int*   colind = (const int*)  d_in[4];
    const int*   colptr = (const int*)  d_in[5];

    const int n = in_sizes[3] - 1;
    float* out = (float*)d_out;

    __half* h_scratch = nullptr;
    cudaGetSymbolAddress((void**)&h_scratch, g_h);
    uint4* wfrag = nullptr;
    cudaGetSymbolAddress((void**)&wfrag, g_wfrag);

    // Stage 0: bake W frags (2048 uint4)
    wfrag_kernel<<<8, 256>>>(weight);

    // Stage 1: GEMM (128 rows per block)
    int gemm_blocks = (n + 127) / 128;
    gemm_mma_kernel<<<gemm_blocks, 256>>>(x, wfrag, colptr, h_scratch, n);

    // Stage 2: aggregate
    int agg_blocks = (n + 7) / 8;
    aggregate_kernel<<<agg_blocks, 256>>>(h_scratch, rowptr, colind, bias,
                                          out, n);
}